// round 16
// baseline (speedup 1.0000x reference)
#include <cuda_runtime.h>
#include <cuda_fp16.h>
#include <math.h>
#include <stdint.h>

// Problem constants
#define BB 4
#define DD 1024
#define NN 4096
#define HH 16
#define KK 128
#define DHH 64

typedef unsigned long long ull;
typedef unsigned int uint;
typedef unsigned short ushort;

// ---------------- scratch (device globals) ----------------
__device__ float g_kp  [(size_t)BB * DD * KK];
__device__ float g_srcp[(size_t)BB * DD * KK];
__device__ float g_scol[KK];
__device__ float g_b1f [2 * DD];
__device__ float g_bqp [DD];

// single-plane fp16 weights
__device__ ushort g_wqp_h [(size_t)DD * DD];
__device__ ushort g_wk_h  [(size_t)DD * DD];
__device__ ushort g_ws1f_h[(size_t)(2 * DD) * (2 * DD)];
__device__ ushort g_ws2_h [(size_t)DD * (2 * DD)];
__device__ ushort g_w1b_h [(size_t)(2 * DD) * DD];
__device__ ushort g_wmTp  [(size_t)DD * DD];
// fp16 activations / operands
__device__ ushort g_xs   [(size_t)BB * NN * DD];
__device__ ushort g_qs   [(size_t)BB * NN * DD];   // also fp32 scratch for W1c (16.8MB)
__device__ ushort g_msgs [(size_t)BB * NN * DD];
__device__ ushort g_hs   [(size_t)BB * NN * 2 * DD];
__device__ ushort g_srcpT[(size_t)BB * KK * DD];
__device__ ushort g_projT[(size_t)KK * NN];

// ---------------- helpers ----------------
__device__ __forceinline__ uint32_t smem_to_u32(const void* p) {
    uint32_t a;
    asm("{ .reg .u64 t; cvta.to.shared.u64 t, %1; cvt.u32.u64 %0, t; }"
        : "=r"(a) : "l"(p));
    return a;
}
__device__ __forceinline__ void sts_v4(uint32_t addr, uint4 v) {
    asm volatile("st.shared.v4.b32 [%0], {%1, %2, %3, %4};"
                 :: "r"(addr), "r"(v.x), "r"(v.y), "r"(v.z), "r"(v.w));
}
__device__ __forceinline__ void ldsm4(uint* r, uint32_t addr) {
    asm volatile("ldmatrix.sync.aligned.m8n8.x4.shared.b16 {%0,%1,%2,%3}, [%4];"
        : "=r"(r[0]), "=r"(r[1]), "=r"(r[2]), "=r"(r[3]) : "r"(addr));
}

// HMMA m16n8k16 fp16 -> fp32
__device__ __forceinline__ void mma16816(float* c, const uint* a, uint b0, uint b1) {
    asm volatile(
        "mma.sync.aligned.m16n8k16.row.col.f32.f16.f16.f32 "
        "{%0,%1,%2,%3}, {%4,%5,%6,%7}, {%8,%9}, {%0,%1,%2,%3};"
        : "+f"(c[0]), "+f"(c[1]), "+f"(c[2]), "+f"(c[3])
        : "r"(a[0]), "r"(a[1]), "r"(a[2]), "r"(a[3]), "r"(b0), "r"(b1));
}
__device__ __forceinline__ uint ex2_f16x2(uint t) {
    uint r;
    asm("ex2.approx.f16x2 %0, %1;" : "=r"(r) : "r"(t));
    return r;
}

// pack 8 consecutive fp32 -> 8 fp16 (one uint4 store)
__device__ __forceinline__ void cvt8(const float* __restrict__ in, ushort* __restrict__ out) {
    float4 f0 = *(const float4*)in;
    float4 f1 = *(const float4*)(in + 4);
    __half2 h0 = __floats2half2_rn(f0.x, f0.y);
    __half2 h1 = __floats2half2_rn(f0.z, f0.w);
    __half2 h2 = __floats2half2_rn(f1.x, f1.y);
    __half2 h3 = __floats2half2_rn(f1.z, f1.w);
    *(uint4*)out = make_uint4(*(uint*)&h0, *(uint*)&h1, *(uint*)&h2, *(uint*)&h3);
}

// ---------------------------------------------------------------------------
// Mega weight prep: 8 elems/thread, fully vectorized.
// regions: [0,512) wq(perm) | [512,1024) wk | [1024,2048) w2 | [2048,4096) w1
// ---------------------------------------------------------------------------
__global__ void prep_all(const float* __restrict__ wq, const float* __restrict__ wk,
                         const float* __restrict__ w2, const float* __restrict__ w1,
                         ushort* __restrict__ wqp, ushort* __restrict__ wkh,
                         ushort* __restrict__ ws2h,
                         ushort* __restrict__ w1a, ushort* __restrict__ w1b)
{
    const int cta = blockIdx.x;
    const int tid = threadIdx.x;
    if (cta < 512) {
        const int i = cta * 2048 + tid * 8;
        const int m = i >> 10, k = i & 1023;
        const int p = (m & 15) * 64 + (m >> 4);
        cvt8(wq + i, wqp + (size_t)p * DD + k);
    } else if (cta < 1024) {
        const int i = (cta - 512) * 2048 + tid * 8;
        cvt8(wk + i, wkh + i);
    } else if (cta < 2048) {
        const int i = (cta - 1024) * 2048 + tid * 8;
        cvt8(w2 + i, ws2h + i);
    } else {
        const int i = (cta - 2048) * 2048 + tid * 8;
        const int m = i >> 11, k = i & 2047;
        if (k < DD) cvt8(w1 + i, w1a + (size_t)m * (2 * DD) + k);
        else        cvt8(w1 + i, w1b + (size_t)m * DD + (k - DD));
    }
}

// ---------------------------------------------------------------------------
// Fused small prep: bias_fold (ctas 0..255) | colsum (256..287) | bias_perm (288..291)
// ---------------------------------------------------------------------------
__global__ void small_prep(const float* __restrict__ w1, const float* __restrict__ bm,
                           const float* __restrict__ b1, float* __restrict__ b1f,
                           const float* __restrict__ proj, float* __restrict__ scol,
                           const float* __restrict__ bq, float* __restrict__ bqp)
{
    const int cta = blockIdx.x;
    const int tid = threadIdx.x;
    if (cta < 256) {
        const int m = cta * 8 + (tid >> 5);
        const int lane = tid & 31;
        float s = 0.f;
#pragma unroll 4
        for (int c = lane; c < DD; c += 32)
            s += w1[(size_t)m * (2 * DD) + DD + c] * bm[c];
#pragma unroll
        for (int o = 16; o; o >>= 1) s += __shfl_xor_sync(0xFFFFFFFFu, s, o);
        if (lane == 0) b1f[m] = b1[m] + s;
    } else if (cta < 288) {
        if (tid < KK) {
            const float* p = proj + (size_t)(cta - 256) * 128 * KK + tid;
            float s = 0.f;
#pragma unroll 8
            for (int m = 0; m < 128; m++) s += p[(size_t)m * KK];
            atomicAdd(&scol[tid], s);
        }
    } else {
        const int p = (cta - 288) * 256 + tid;
        const int d = (p & 63) * 16 + (p >> 6);
        bqp[p] = bq[d];
    }
}

// fp32 [B, C, N] -> fp16 [B, N, C]
__global__ void transpose_half(const float* __restrict__ in, ushort* __restrict__ out,
                               int C, int Nw) {
    __shared__ float tile[32][33];
    const int b = blockIdx.z;
    const int n0 = blockIdx.x * 32, c0 = blockIdx.y * 32;
    const int tx = threadIdx.x, ty = threadIdx.y;
    const float* inb = in + ((size_t)b * C + c0) * Nw + n0;
#pragma unroll
    for (int i = 0; i < 32; i += 8)
        tile[ty + i][tx] = inb[(size_t)(ty + i) * Nw + tx];
    __syncthreads();
    ushort* ob = out + ((size_t)b * Nw + n0) * C + c0;
#pragma unroll
    for (int i = 0; i < 32; i += 8)
        ob[(size_t)(ty + i) * C + tx] = __half_as_ushort(__float2half_rn(tile[tx][ty + i]));
}

// Permuted merge transpose: out[p][j] = fp16(merge_w[j][c]), p=(c%16)*64+c/16
__global__ void transpose_perm(const float* __restrict__ in, ushort* __restrict__ out) {
    __shared__ float tile[32][33];
    const int n0 = blockIdx.x * 32, c0 = blockIdx.y * 32;
    const int tx = threadIdx.x, ty = threadIdx.y;
    const float* inb = in + (size_t)(c0) * DD + n0;
#pragma unroll
    for (int i = 0; i < 32; i += 8)
        tile[ty + i][tx] = inb[(size_t)(ty + i) * DD + tx];
    __syncthreads();
#pragma unroll
    for (int i = 0; i < 32; i += 8) {
        const int r = n0 + ty + i;
        const int p = (r & 15) * 64 + (r >> 4);
        out[(size_t)p * DD + c0 + tx] =
            __half_as_ushort(__float2half_rn(tile[tx][ty + i]));
    }
}

// W1c: add two fp32 partial slices -> fp16 into ws1fh second half
__global__ void w1c_cvt2(const float* __restrict__ a, const float* __restrict__ b,
                         ushort* __restrict__ out) {
    const int i = (blockIdx.x * 256 + threadIdx.x) * 8;   // over 2048*1024
    const int m = i >> 10, k = i & 1023;
    float4 f0 = *(const float4*)(a + i);
    float4 f1 = *(const float4*)(a + i + 4);
    float4 g0 = *(const float4*)(b + i);
    float4 g1 = *(const float4*)(b + i + 4);
    __half2 h0 = __floats2half2_rn(f0.x + g0.x, f0.y + g0.y);
    __half2 h1 = __floats2half2_rn(f0.z + g0.z, f0.w + g0.w);
    __half2 h2 = __floats2half2_rn(f1.x + g1.x, f1.y + g1.y);
    __half2 h3 = __floats2half2_rn(f1.z + g1.z, f1.w + g1.w);
    *(uint4*)(out + (size_t)m * (2 * DD) + DD + k) =
        make_uint4(*(uint*)&h0, *(uint*)&h1, *(uint*)&h2, *(uint*)&h3);
}

// ---------------------------------------------------------------------------
// Warp-level HMMA GEMM (single-plane fp16 A).
// MODE 0: fp32 out (+bias); MODE 1: +bias fp16-transpose out [B,Nw,M];
// MODE 2: +bias/BN/ReLU fp16-transpose out;
// MODE 4: fp32 out + bias[m]*colS[n]  (colS passed via gamma).
// ---------------------------------------------------------------------------
#define STG_S 136

template <int MODE>
__global__ void __launch_bounds__(256, 2) hmma_gemm(
    const ushort* __restrict__ Aptr,
    const ushort* __restrict__ B1,
    const ushort* __restrict__ B2,
    const float* __restrict__ bias,
    const float* __restrict__ gamma,
    const float* __restrict__ beta,
    const float* __restrict__ mean,
    const float* __restrict__ var,
    float* __restrict__ outF,
    ushort* __restrict__ outT,
    int M, int Kd, int Nw, int K1, int ostr)
{
    constexpr uint32_t PLB   = 18432u;
    constexpr uint32_t SMBUF = 36864u;

    extern __shared__ char smem[];
    const uint32_t sb = smem_to_u32(smem);

    const int tid  = threadIdx.x;
    const int wid  = tid >> 5;
    const int lane = tid & 31;
    const int m0 = blockIdx.y * 128;
    const int n0 = blockIdx.x * 128;
    const int bb = blockIdx.z;

    const int wm = wid & 3;
    const int wn = wid >> 2;
    const int K2 = Kd - K1;
    const int fr = lane >> 2;
    const int fc = (lane & 3) * 2;

    float c[2][8][4];
#pragma unroll
    for (int mt = 0; mt < 2; mt++)
#pragma unroll
        for (int nt = 0; nt < 8; nt++)
#pragma unroll
            for (int j = 0; j < 4; j++) c[mt][nt][j] = 0.f;

    const int nc = Kd >> 6;
    uint4 pa[4], pb[4];

    auto ldg_tile = [&](int ch) {
        const int k0 = ch * 64;
        const ushort* Ab = Aptr + (size_t)m0 * Kd;
#pragma unroll
        for (int it = 0; it < 4; it++) {
            const int idx = it * 256 + tid;
            const int row = idx >> 3, q4 = idx & 7;
            pa[it] = *(const uint4*)(Ab + (size_t)row * Kd + k0 + q4 * 8);
        }
        const ushort* Bsrc; int kloc, kstride;
        if (k0 < K1) { Bsrc = B1; kloc = k0;      kstride = K1; }
        else         { Bsrc = B2; kloc = k0 - K1; kstride = K2; }
        const ushort* Bb = Bsrc + ((size_t)bb * Nw + n0) * kstride + kloc;
#pragma unroll
        for (int it = 0; it < 4; it++) {
            const int idx = it * 256 + tid;
            const int row = idx >> 3, q4 = idx & 7;
            pb[it] = *(const uint4*)(Bb + (size_t)row * kstride + q4 * 8);
        }
    };
    auto sts_tile = [&](int buf) {
        const uint32_t base = sb + buf * SMBUF;
#pragma unroll
        for (int it = 0; it < 4; it++) {
            const int idx = it * 256 + tid;
            const int row = idx >> 3, q4 = idx & 7;
            sts_v4(base + (uint32_t)row * 144 + q4 * 16, pa[it]);
            sts_v4(base + PLB + (uint32_t)row * 144 + q4 * 16, pb[it]);
        }
    };

    ldg_tile(0);
    sts_tile(0);
    __syncthreads();

    const uint32_t aOff = (uint32_t)(wm * 32 + (lane & 15)) * 144 + ((lane >> 4) & 1) * 16;
    const uint32_t bOff = (uint32_t)(wn * 64 + (lane & 7) + ((lane & 16) ? 8 : 0)) * 144
                        + ((lane & 8) ? 16 : 0);

    for (int ch = 0; ch < nc; ch++) {
        const uint32_t base = sb + (ch & 1) * SMBUF;
        if (ch + 1 < nc) ldg_tile(ch + 1);
#pragma unroll
        for (int ksb = 0; ksb < 128; ksb += 32) {
            uint ah[2][4];
            ldsm4(ah[0], base + aOff + ksb);
            ldsm4(ah[1], base + aOff + 2304 + ksb);
            uint bh[4][4];
#pragma unroll
            for (int np = 0; np < 4; np++)
                ldsm4(bh[np], base + PLB + bOff + np * 2304 + ksb);
#pragma unroll
            for (int np = 0; np < 4; np++)
#pragma unroll
                for (int sub = 0; sub < 2; sub++) {
                    const int nt = np * 2 + sub;
                    const uint b0 = bh[np][sub * 2], b1 = bh[np][sub * 2 + 1];
#pragma unroll
                    for (int mt = 0; mt < 2; mt++)
                        mma16816(c[mt][nt], ah[mt], b0, b1);
                }
        }
        if (ch + 1 < nc) {
            sts_tile((ch + 1) & 1);
            __syncthreads();
        }
    }

    // ---- epilogue ----
    if (MODE == 0 || MODE == 4) {
        const int cm = m0 + wm * 32 + fr;
        const int cn = n0 + wn * 64 + fc;
#pragma unroll
        for (int mt = 0; mt < 2; mt++) {
            const int mlo = cm + mt * 16;
            const int mhi = mlo + 8;
            const float bi0 = bias[mlo], bi1 = bias[mhi];
#pragma unroll
            for (int nt = 0; nt < 8; nt++) {
                const int n = cn + nt * 8;
                float s0 = 1.f, s1 = 1.f;
                if (MODE == 4) { s0 = gamma[n]; s1 = gamma[n + 1]; }
                *(float2*)(outF + ((size_t)bb * M + mlo) * ostr + n) =
                    make_float2(c[mt][nt][0] + bi0 * s0, c[mt][nt][1] + bi0 * s1);
                *(float2*)(outF + ((size_t)bb * M + mhi) * ostr + n) =
                    make_float2(c[mt][nt][2] + bi1 * s0, c[mt][nt][3] + bi1 * s1);
            }
        }
    } else {
        float* stg = (float*)smem;
        uint* ob = (uint*)(outT + (size_t)bb * Nw * M);
#pragma unroll
        for (int p = 0; p < 2; p++) {
            __syncthreads();
            if (wn == p) {
#pragma unroll
                for (int mt = 0; mt < 2; mt++) {
                    const int mloL = wm * 32 + mt * 16 + fr;
                    const int mhiL = mloL + 8;
                    const int mlo = m0 + mloL, mhi = m0 + mhiL;
                    float sc0 = 1.f, sh0 = bias[mlo];
                    float sc1 = 1.f, sh1 = bias[mhi];
                    if (MODE == 2) {
                        sc0 = gamma[mlo] * rsqrtf(var[mlo] + 1e-3f);
                        sh0 = beta[mlo] + (sh0 - mean[mlo]) * sc0;
                        sc1 = gamma[mhi] * rsqrtf(var[mhi] + 1e-3f);
                        sh1 = beta[mhi] + (sh1 - mean[mhi]) * sc1;
                    }
#pragma unroll
                    for (int nt = 0; nt < 8; nt++) {
                        const int nl = fc + nt * 8;
                        float v0 = fmaf(c[mt][nt][0], sc0, sh0);
                        float v1 = fmaf(c[mt][nt][1], sc0, sh0);
                        float v2 = fmaf(c[mt][nt][2], sc1, sh1);
                        float v3 = fmaf(c[mt][nt][3], sc1, sh1);
                        if (MODE == 2) {
                            v0 = fmaxf(v0, 0.f); v1 = fmaxf(v1, 0.f);
                            v2 = fmaxf(v2, 0.f); v3 = fmaxf(v3, 0.f);
                        }
                        stg[(nl)     * STG_S + mloL] = v0;
                        stg[(nl + 1) * STG_S + mloL] = v1;
                        stg[(nl)     * STG_S + mhiL] = v2;
                        stg[(nl + 1) * STG_S + mhiL] = v3;
                    }
                }
            }
            __syncthreads();
            const int nb = n0 + p * 64;
#pragma unroll 4
            for (int i = 0; i < 16; i++) {
                const int idx = i * 256 + tid;
                const int nn = idx >> 6;
                const int mp = idx & 63;
                const float* s = stg + nn * STG_S + mp * 2;
                const uint u = (uint)__half_as_ushort(__float2half_rn(s[0]))
                             | ((uint)__half_as_ushort(__float2half_rn(s[1])) << 16);
                ob[(size_t)(nb + nn) * (M >> 1) + (m0 >> 1) + mp] = u;
            }
        }
    }
}

// ---------------------------------------------------------------------------
// Split-K fp16 HMMA: srcp[r,c] += fp16(source[r,:]) . projT[c,:]
// ---------------------------------------------------------------------------
__global__ void __launch_bounds__(256, 2) hmma_splitk(
    const float* __restrict__ A,
    const ushort* __restrict__ Bp,
    float* __restrict__ C)
{
    constexpr uint32_t PLB = 18432;
    constexpr uint32_t SMBUF = 36864;
    extern __shared__ char smem[];
    const uint32_t sb = smem_to_u32(smem);

    const int tid  = threadIdx.x;
    const int wid  = tid >> 5;
    const int lane = tid & 31;
    const int m0 = blockIdx.y * 128;
    const int kbase = blockIdx.x * 512;
    const int Kd = NN;

    const int wm = wid & 3;
    const int wn = wid >> 2;
    const int fr = lane >> 2;
    const int fc = (lane & 3) * 2;

    float c[2][8][4];
#pragma unroll
    for (int mt = 0; mt < 2; mt++)
#pragma unroll
        for (int nt = 0; nt < 8; nt++)
#pragma unroll
            for (int j = 0; j < 4; j++) c[mt][nt][j] = 0.f;

    uint4 pa[4], pb[4];
    auto ldg_tile = [&](int ch) {
        const int k0 = kbase + ch * 64;
        const float* Ab = A + (size_t)m0 * Kd;
#pragma unroll
        for (int it = 0; it < 4; it++) {
            const int idx = it * 256 + tid;
            const int row = idx >> 3, q4 = idx & 7;
            const float* ap = Ab + (size_t)row * Kd + k0 + q4 * 8;
            float4 f0 = *(const float4*)ap;
            float4 f1 = *(const float4*)(ap + 4);
            __half2 h0 = __floats2half2_rn(f0.x, f0.y);
            __half2 h1 = __floats2half2_rn(f0.z, f0.w);
            __half2 h2 = __floats2half2_rn(f1.x, f1.y);
            __half2 h3 = __floats2half2_rn(f1.z, f1.w);
            pa[it] = make_uint4(*(uint*)&h0, *(uint*)&h1, *(uint*)&h2, *(uint*)&h3);
        }
#pragma unroll
        for (int it = 0; it < 4; it++) {
            const int idx = it * 256 + tid;
            const int row = idx >> 3, q4 = idx & 7;
            pb[it] = *(const uint4*)(Bp + (size_t)row * Kd + k0 + q4 * 8);
        }
    };
    auto sts_tile = [&](int buf) {
        const uint32_t base = sb + buf * SMBUF;
#pragma unroll
        for (int it = 0; it < 4; it++) {
            const int idx = it * 256 + tid;
            const int row = idx >> 3, q4 = idx & 7;
            sts_v4(base + (uint32_t)row * 144 + q4 * 16, pa[it]);
            sts_v4(base + PLB + (uint32_t)row * 144 + q4 * 16, pb[it]);
        }
    };

    ldg_tile(0);
    sts_tile(0);
    __syncthreads();

    const uint32_t aOff = (uint32_t)(wm * 32 + (lane & 15)) * 144 + ((lane >> 4) & 1) * 16;
    const uint32_t bOff = (uint32_t)(wn * 64 + (lane & 7) + ((lane & 16) ? 8 : 0)) * 144
                        + ((lane & 8) ? 16 : 0);

    for (int ch = 0; ch < 8; ch++) {
        const uint32_t base = sb + (ch & 1) * SMBUF;
        if (ch + 1 < 8) ldg_tile(ch + 1);
#pragma unroll
        for (int ksb = 0; ksb < 128; ksb += 32) {
            uint ah[2][4];
            ldsm4(ah[0], base + aOff + ksb);
            ldsm4(ah[1], base + aOff + 2304 + ksb);
            uint bh[4][4];
#pragma unroll
            for (int np = 0; np < 4; np++)
                ldsm4(bh[np], base + PLB + bOff + np * 2304 + ksb);
#pragma unroll
            for (int np = 0; np < 4; np++)
#pragma unroll
                for (int sub = 0; sub < 2; sub++) {
                    const int nt = np * 2 + sub;
#pragma unroll
                    for (int mt = 0; mt < 2; mt++)
                        mma16816(c[mt][nt], ah[mt], bh[np][sub * 2], bh[np][sub * 2 + 1]);
                }
        }
        if (ch + 1 < 8) {
            sts_tile((ch + 1) & 1);
            __syncthreads();
        }
    }

    const int cm = m0 + wm * 32 + fr;
    const int cn = wn * 64 + fc;
#pragma unroll
    for (int mt = 0; mt < 2; mt++) {
        const int mlo = cm + mt * 16;
        const int mhi = mlo + 8;
#pragma unroll
        for (int nt = 0; nt < 8; nt++) {
            const int n = cn + nt * 8;
            atomicAdd(&C[(size_t)mlo * KK + n],     c[mt][nt][0]);
            atomicAdd(&C[(size_t)mlo * KK + n + 1], c[mt][nt][1]);
            atomicAdd(&C[(size_t)mhi * KK + n],     c[mt][nt][2]);
            atomicAdd(&C[(size_t)mhi * KK + n + 1], c[mt][nt][3]);
        }
    }
}

// ---------------------------------------------------------------------------
// W1c 2-slice split-K, NO atomics: each kslice direct-stores fp32 partials
// to its own region.  C_slice[m,n] = sum_{k in slice} w1b[m,k] * wmTp[n,k]
// grid (2 kslices, 16 mtiles, 8 ntiles) = 256 CTAs -> 2 CTAs/SM overlap.
// ---------------------------------------------------------------------------
__global__ void __launch_bounds__(256, 2) w1c_splitk2(
    const ushort* __restrict__ A,
    const ushort* __restrict__ Bp,
    float* __restrict__ C)
{
    constexpr uint32_t PLB = 18432;
    constexpr uint32_t SMBUF = 36864;
    extern __shared__ char smem[];
    const uint32_t sb = smem_to_u32(smem);

    const int tid  = threadIdx.x;
    const int wid  = tid >> 5;
    const int lane = tid & 31;
    const int kbase = blockIdx.x * 512;
    const int m0 = blockIdx.y * 128;
    const int n0 = blockIdx.z * 128;
    const int Kd = DD;
    float* Cs = C + (size_t)blockIdx.x * (2 * DD) * DD;

    const int wm = wid & 3;
    const int wn = wid >> 2;
    const int fr = lane >> 2;
    const int fc = (lane & 3) * 2;

    float c[2][8][4];
#pragma unroll
    for (int mt = 0; mt < 2; mt++)
#pragma unroll
        for (int nt = 0; nt < 8; nt++)
#pragma unroll
            for (int j = 0; j < 4; j++) c[mt][nt][j] = 0.f;

    uint4 pa[4], pb[4];
    auto ldg_tile = [&](int ch) {
        const int k0 = kbase + ch * 64;
        const ushort* Ab = A + (size_t)m0 * Kd;
        const ushort* Bb = Bp + (size_t)n0 * Kd;
#pragma unroll
        for (int it = 0; it < 4; it++) {
            const int idx = it * 256 + tid;
            const int row = idx >> 3, q4 = idx & 7;
            pa[it] = *(const uint4*)(Ab + (size_t)row * Kd + k0 + q4 * 8);
            pb[it] = *(const uint4*)(Bb + (size_t)row * Kd + k0 + q4 * 8);
        }
    };
    auto sts_tile = [&](int buf) {
        const uint32_t base = sb + buf * SMBUF;
#pragma unroll
        for (int it = 0; it < 4; it++) {
            const int idx = it * 256 + tid;
            const int row = idx >> 3, q4 = idx & 7;
            sts_v4(base + (uint32_t)row * 144 + q4 * 16, pa[it]);
            sts_v4(base + PLB + (uint32_t)row * 144 + q4 * 16, pb[it]);
        }
    };

    ldg_tile(0);
    sts_tile(0);
    __syncthreads();

    const uint32_t aOff = (uint32_t)(wm * 32 + (lane & 15)) * 144 + ((lane >> 4) & 1) * 16;
    const uint32_t bOff = (uint32_t)(wn * 64 + (lane & 7) + ((lane & 16) ? 8 : 0)) * 144
                        + ((lane & 8) ? 16 : 0);

    for (int ch = 0; ch < 8; ch++) {
        const uint32_t base = sb + (ch & 1) * SMBUF;
        if (ch + 1 < 8) ldg_tile(ch + 1);
#pragma unroll
        for (int ksb = 0; ksb < 128; ksb += 32) {
            uint ah[2][4];
            ldsm4(ah[0], base + aOff + ksb);
            ldsm4(ah[1], base + aOff + 2304 + ksb);
            uint bh[4][4];
#pragma unroll
            for (int np = 0; np < 4; np++)
                ldsm4(bh[np], base + PLB + bOff + np * 2304 + ksb);
#pragma unroll
            for (int np = 0; np < 4; np++)
#pragma unroll
                for (int sub = 0; sub < 2; sub++) {
                    const int nt = np * 2 + sub;
#pragma unroll
                    for (int mt = 0; mt < 2; mt++)
                        mma16816(c[mt][nt], ah[mt], bh[np][sub * 2], bh[np][sub * 2 + 1]);
                }
        }
        if (ch + 1 < 8) {
            sts_tile((ch + 1) & 1);
            __syncthreads();
        }
    }

    const int cm = m0 + wm * 32 + fr;
    const int cn = n0 + wn * 64 + fc;
#pragma unroll
    for (int mt = 0; mt < 2; mt++) {
        const int mlo = cm + mt * 16;
        const int mhi = mlo + 8;
#pragma unroll
        for (int nt = 0; nt < 8; nt++) {
            const int n = cn + nt * 8;
            *(float2*)(Cs + (size_t)mlo * DD + n) = make_float2(c[mt][nt][0], c[mt][nt][1]);
            *(float2*)(Cs + (size_t)mhi * DD + n) = make_float2(c[mt][nt][2], c[mt][nt][3]);
        }
    }
}

// ---------------------------------------------------------------------------
// Tensor-core attention (fp16x2 MUFU exp, 2 CTAs/SM, reg-reuse).
// ---------------------------------------------------------------------------
#define AT_Q   0
#define AT_K1  18432
#define AT_K2  36864
#define AT_RS  54272
#define AT_SMEM 54784

__global__ void __launch_bounds__(256, 2) attn_mma(
    const ushort* __restrict__ qs,
    const float* __restrict__ kp,
    ushort* __restrict__ msgs)
{
    extern __shared__ char smem[];
    const uint32_t sb = smem_to_u32(smem);
    float* rowsum = (float*)(smem + AT_RS);

    const int tid = threadIdx.x;
    const int wid = tid >> 5, lane = tid & 31;
    const int wm = wid & 3, wn = wid >> 2;
    const int fr = lane >> 2, fc = (lane & 3) * 2;
    const int n0 = blockIdx.x * 128;
    const int h = blockIdx.y;
    const int b = blockIdx.z;

    // Q tile [128][64] fp16 -> smem stride 144B
    {
        const ushort* qb = qs + ((size_t)b * NN + n0) * DD + (size_t)h * DHH;
#pragma unroll
        for (int it = 0; it < 4; it++) {
            const int idx = it * 256 + tid;
            const int row = idx >> 3, q4 = idx & 7;
            uint4 v = *(const uint4*)(qb + (size_t)row * DD + q4 * 8);
            sts_v4(sb + AT_Q + (uint32_t)row * 144 + q4 * 16, v);
        }
    }
    // K fp32 [64 dh][128 kk] (float4 loads) -> K1 [kk][dh] + K2 [dh][kk]
    {
        const float* kb = kp + ((size_t)b * DD + h) * KK;
        ushort* K1 = (ushort*)(smem + AT_K1);
        ushort* K2 = (ushort*)(smem + AT_K2);
#pragma unroll 4
        for (int i = 0; i < 8; i++) {
            const int e = i * 256 + tid;
            const int dh = e >> 5, k4 = (e & 31) * 4;
            const float4 v = *(const float4*)(kb + (size_t)dh * HH * KK + k4);
            const ushort h0 = __half_as_ushort(__float2half_rn(v.x));
            const ushort h1 = __half_as_ushort(__float2half_rn(v.y));
            const ushort h2 = __half_as_ushort(__float2half_rn(v.z));
            const ushort h3 = __half_as_ushort(__float2half_rn(v.w));
            const __half2 p01 = __floats2half2_rn(v.x, v.y);
            const __half2 p23 = __floats2half2_rn(v.z, v.w);
            *(uint*)&K2[dh * 136 + k4]     = *(const uint*)&p01;
            *(uint*)&K2[dh * 136 + k4 + 2] = *(const uint*)&p23;
            K1[(k4)     * 72 + dh] = h0;
            K1[(k4 + 1) * 72 + dh] = h1;
            K1[(k4 + 2) * 72 + dh] = h2;
            K1[(k4 + 3) * 72 + dh] = h3;
        }
    }
    if (tid < 128) rowsum[tid] = 0.f;
    __syncthreads();

    // MMA1: S[n][kk]
    float c[2][8][4];
#pragma unroll
    for (int mt = 0; mt < 2; mt++)
#pragma unroll
        for (int nt = 0; nt < 8; nt++)
#pragma unroll
            for (int j = 0; j < 4; j++) c[mt][nt][j] = 0.f;

    const uint32_t aOff = (uint32_t)(wm * 32 + (lane & 15)) * 144 + ((lane >> 4) & 1) * 16;
    const uint32_t bOff = (uint32_t)(wn * 64 + (lane & 7) + ((lane & 16) ? 8 : 0)) * 144
                        + ((lane & 8) ? 16 : 0);
#pragma unroll
    for (int ksb = 0; ksb < 128; ksb += 32) {
        uint ah[2][4];
        ldsm4(ah[0], sb + AT_Q + aOff + ksb);
        ldsm4(ah[1], sb + AT_Q + aOff + 2304 + ksb);
#pragma unroll
        for (int np = 0; np < 4; np++) {
            uint bh[4];
            ldsm4(bh, sb + AT_K1 + bOff + np * 2304 + ksb);
#pragma unroll
            for (int sub = 0; sub < 2; sub++)
#pragma unroll
                for (int mt = 0; mt < 2; mt++)
                    mma16816(c[mt][np * 2 + sub], ah[mt], bh[sub * 2], bh[sub * 2 + 1]);
        }
    }

    // P = 2^(s*C1 + C2) via ex2.approx.f16x2 ; rowsum fp32
    const float C1 = 0.18033688f;    // log2(e)/8
    const float C2 = -5.7707801f;    // -4*log2(e)
    uint ph[2][8][2];
#pragma unroll
    for (int mt = 0; mt < 2; mt++) {
        float r0 = 0.f, r1 = 0.f;
#pragma unroll
        for (int nt = 0; nt < 8; nt++) {
            const float t0 = fmaf(c[mt][nt][0], C1, C2);
            const float t1 = fmaf(c[mt][nt][1], C1, C2);
            const float t2 = fmaf(c[mt][nt][2], C1, C2);
            const float t3 = fmaf(c[mt][nt][3], C1, C2);
            const __half2 ta = __floats2half2_rn(t0, t1);
            const __half2 tb = __floats2half2_rn(t2, t3);
            const uint ea = ex2_f16x2(*(const uint*)&ta);
            const uint eb = ex2_f16x2(*(const uint*)&tb);
            ph[mt][nt][0] = ea;
            ph[mt][nt][1] = eb;
            const float2 fa = __half22float2(*(const __half2*)&ea);
            const float2 fb = __half22float2(*(const __half2*)&eb);
            r0 += fa.x + fa.y;
            r1 += fb.x + fb.y;
        }
        r0 += __shfl_xor_sync(0xFFFFFFFFu, r0, 1);
        r0 += __shfl_xor_sync(0xFFFFFFFFu, r0, 2);
        r1 += __shfl_xor_sync(0xFFFFFFFFu, r1, 1);
        r1 += __shfl_xor_sync(0xFFFFFFFFu, r1, 2);
        if ((lane & 3) == 0) {
            atomicAdd(&rowsum[wm * 32 + mt * 16 + fr], r0);
            atomicAdd(&rowsum[wm * 32 + mt * 16 + fr + 8], r1);
        }
    }

    // MMA2: reuse c as O accumulators
#pragma unroll
    for (int mt = 0; mt < 2; mt++)
#pragma unroll
        for (int nt = 0; nt < 8; nt++)
#pragma unroll
            for (int j = 0; j < 4; j++) c[mt][nt][j] = 0.f;

    const uint32_t b2Off = (uint32_t)((lane & 7) + ((lane & 16) ? 8 : 0)) * 272
                         + ((lane & 8) ? 16 : 0) + (uint32_t)wn * 128;
#pragma unroll
    for (int s = 0; s < 4; s++) {
        uint a2[2][4];
#pragma unroll
        for (int mt = 0; mt < 2; mt++) {
            a2[mt][0] = ph[mt][2 * s][0];
            a2[mt][1] = ph[mt][2 * s][1];
            a2[mt][2] = ph[mt][2 * s + 1][0];
            a2[mt][3] = ph[mt][2 * s + 1][1];
        }
#pragma unroll
        for (int np = 0; np < 4; np++) {
            uint bh[4];
            ldsm4(bh, sb + AT_K2 + b2Off + (uint32_t)np * 16 * 272 + s * 32);
#pragma unroll
            for (int sub = 0; sub < 2; sub++)
#pragma unroll
                for (int mt = 0; mt < 2; mt++)
                    mma16816(c[mt][np * 2 + sub], a2[mt], bh[sub * 2], bh[sub * 2 + 1]);
        }
    }

    // merge partials, normalize, write fp16 head-major
    __syncthreads();
    float* stg = (float*)smem;
    if (tid < 128) rowsum[tid] = 1.f / rowsum[tid];
    const int mb = wm * 32 + fr;
    if (wn == 0) {
#pragma unroll
        for (int mt = 0; mt < 2; mt++)
#pragma unroll
            for (int nt = 0; nt < 8; nt++) {
                const int col = nt * 8 + fc;
                stg[(mb + mt * 16)     * 68 + col]     = c[mt][nt][0];
                stg[(mb + mt * 16)     * 68 + col + 1] = c[mt][nt][1];
                stg[(mb + mt * 16 + 8) * 68 + col]     = c[mt][nt][2];
                stg[(mb + mt * 16 + 8) * 68 + col + 1] = c[mt][nt][3];
            }
    }
    __syncthreads();
    if (wn == 1) {
#pragma unroll
        for (int mt = 0; mt < 2; mt++)
#pragma unroll
            for (int nt = 0; nt < 8; nt++) {
                const int col = nt * 8 + fc;
                stg[(mb + mt * 16)     * 68 + col]     += c[mt][nt][0];
                stg[(mb + mt * 16)     * 68 + col + 1] += c[mt][nt][1];
                stg[(mb + mt * 16 + 8) * 68 + col]     += c[mt][nt][2];
                stg[(mb + mt * 16 + 8) * 68 + col + 1] += c[mt][nt][3];
            }
    }
    __syncthreads();

    uint* ob = (uint*)(msgs + ((size_t)b * NN + n0) * DD + (size_t)h * DHH);
#pragma unroll 4
    for (int i = 0; i < 16; i++) {
        const int idx = i * 256 + tid;
        const int nn = idx >> 5;
        const int dq = idx & 31;
        const float inv = rowsum[nn];
        const float v0 = stg[nn * 68 + dq * 2]     * inv;
        const float v1 = stg[nn * 68 + dq * 2 + 1] * inv;
        const uint u = (uint)__half_as_ushort(__float2half_rn(v0))
                     | ((uint)__half_as_ushort(__float2half_rn(v1)) << 16);
        ob[(size_t)nn * (DD / 2) + dq] = u;
    }
}

// ---------------------------------------------------------------------------
extern "C" void kernel_launch(void* const* d_in, const int* in_sizes, int n_in,
                              void* d_out, int out_size)
{
    const float* x       = (const float*)d_in[0];
    const float* source  = (const float*)d_in[1];
    const float* to_q_w  = (const float*)d_in[2];
    const float* to_q_b  = (const float*)d_in[3];
    const float* to_k_w  = (const float*)d_in[4];
    const float* to_k_b  = (const float*)d_in[5];
    const float* proj_k  = (const float*)d_in[6];
    const float* merge_w = (const float*)d_in[7];
    const float* merge_b = (const float*)d_in[8];
    const float* mlp_w1  = (const float*)d_in[9];
    const float* mlp_b1  = (const float*)d_in[10];
    const float* bn_g    = (const float*)d_in[11];
    const float* bn_b    = (const float*)d_in[12];
    const float* bn_m    = (const float*)d_in[13];
    const float* bn_v    = (const float*)d_in[14];
    const float* mlp_w2  = (const float*)d_in[15];
    const float* mlp_b2  = (const float*)d_in[16];
    float* out = (float*)d_out;

    float *kp, *srcp, *scol, *b1f, *bqp;
    ushort *wqp, *wkh, *ws1fh, *ws2h, *w1bh, *wmTp, *xs, *qs, *msgs, *hs, *srcpT, *projT;
    cudaGetSymbolAddress((void**)&kp,   g_kp);
    cudaGetSymbolAddress((void**)&srcp, g_srcp);
    cudaGetSymbolAddress((void**)&scol, g_scol);
    cudaGetSymbolAddress((void**)&b1f,  g_b1f);
    cudaGetSymbolAddress((void**)&bqp,  g_bqp);
    cudaGetSymbolAddress((void**)&wqp,  g_wqp_h);
    cudaGetSymbolAddress((void**)&wkh,  g_wk_h);
    cudaGetSymbolAddress((void**)&ws1fh,g_ws1f_h);
    cudaGetSymbolAddress((void**)&ws2h, g_ws2_h);
    cudaGetSymbolAddress((void**)&w1bh, g_w1b_h);
    cudaGetSymbolAddress((void**)&wmTp, g_wmTp);
    cudaGetSymbolAddress((void**)&xs,   g_xs);
    cudaGetSymbolAddress((void**)&qs,   g_qs);
    cudaGetSymbolAddress((void**)&msgs, g_msgs);
    cudaGetSymbolAddress((void**)&hs,   g_hs);
    cudaGetSymbolAddress((void**)&srcpT,g_srcpT);
    cudaGetSymbolAddress((void**)&projT,g_projT);

    float* w1c_tmp = (float*)qs;   // 16.8 MB scratch inside g_qs (33.5 MB)

    const int SM1 = 2 * 36864;
    cudaFuncSetAttribute(hmma_gemm<0>, cudaFuncAttributeMaxDynamicSharedMemorySize, SM1);
    cudaFuncSetAttribute(hmma_gemm<1>, cudaFuncAttributeMaxDynamicSharedMemorySize, SM1);
    cudaFuncSetAttribute(hmma_gemm<2>, cudaFuncAttributeMaxDynamicSharedMemorySize, SM1);
    cudaFuncSetAttribute(hmma_gemm<4>, cudaFuncAttributeMaxDynamicSharedMemorySize, SM1);
    cudaFuncSetAttribute(hmma_splitk, cudaFuncAttributeMaxDynamicSharedMemorySize, SM1);
    cudaFuncSetAttribute(w1c_splitk2, cudaFuncAttributeMaxDynamicSharedMemorySize, SM1);
    cudaFuncSetAttribute(attn_mma, cudaFuncAttributeMaxDynamicSharedMemorySize, AT_SMEM);

    // 0) fused weight prep + small prep
    prep_all<<<4096, 256>>>(to_q_w, to_k_w, mlp_w2, mlp_w1,
                            wqp, wkh, ws2h, ws1fh, w1bh);
    cudaMemsetAsync(scol, 0, sizeof(float) * KK);
    small_prep<<<292, 256>>>(mlp_w1, merge_b, mlp_b1, b1f, proj_k, scol, to_q_b, bqp);
    transpose_perm<<<dim3(DD / 32, DD / 32), dim3(32, 8)>>>(merge_w, wmTp);

    // W1c = W1b @ Wm (perm cols): 2-slice split-K, no atomics, then add+convert
    w1c_splitk2<<<dim3(2, 16, 8), 256, SM1>>>(w1bh, wmTp, w1c_tmp);
    w1c_cvt2<<<1024, 256>>>(w1c_tmp, w1c_tmp + (size_t)(2 * DD) * DD, ws1fh);

    // x transpose, proj transpose
    transpose_half<<<dim3(NN / 32, DD / 32, BB), dim3(32, 8)>>>(x, xs, DD, NN);
    transpose_half<<<dim3(KK / 32, NN / 32, 1), dim3(32, 8)>>>(proj_k, projT, NN, KK);

    // 1) Linformer fold: kp = Wk @ (src @ proj) + bk * colsum(proj)
    cudaMemsetAsync(srcp, 0, sizeof(float) * (size_t)BB * DD * KK);
    hmma_splitk<<<dim3(8, (BB * DD) / 128), 256, SM1>>>(source, projT, srcp);
    transpose_half<<<dim3(KK / 32, DD / 32, BB), dim3(32, 8)>>>(srcp, srcpT, DD, KK);
    hmma_gemm<4><<<dim3(1, DD / 128, BB), 256, SM1>>>(
        wkh, srcpT, srcpT, to_k_b, scol, nullptr, nullptr, nullptr,
        kp, nullptr, DD, DD, KK, DD, KK);

    // 2) q = Wq @ x + bq  (fp16 head-major transposed out)
    hmma_gemm<1><<<dim3(NN / 128, DD / 128, BB), 256, SM1>>>(
        wqp, xs, xs, bqp, nullptr, nullptr, nullptr, nullptr,
        nullptr, qs, DD, DD, NN, DD, 0);

    // 3) tensor-core attention -> msgs fp16 head-major
    attn_mma<<<dim3(NN / 128, HH, BB), 256, AT_SMEM>>>(qs, kp, msgs);

    // 4) h = relu(BN([W1a | W1c'] @ concat(x, msg) + b1'))
    hmma_gemm<2><<<dim3(NN / 128, (2 * DD) / 128, BB), 256, SM1>>>(
        ws1fh, xs, msgs, b1f, bn_g, bn_b, bn_m, bn_v,
        nullptr, hs, 2 * DD, 2 * DD, NN, DD, 0);

    // 5) out = W2 @ h + b2  (fp32 out)
    hmma_gemm<0><<<dim3(NN / 128, DD / 128, BB), 256, SM1>>>(
        ws2h, hs, hs, mlp_b2, nullptr, nullptr, nullptr, nullptr,
        out, nullptr, DD, 2 * DD, NN, 2 * DD, NN);
}

// round 17
// speedup vs baseline: 1.5560x; 1.5560x over previous
#include <cuda_runtime.h>
#include <cuda_fp16.h>
#include <math.h>
#include <stdint.h>

// Problem constants
#define BB 4
#define DD 1024
#define NN 4096
#define HH 16
#define KK 128
#define DHH 64

typedef unsigned long long ull;
typedef unsigned int uint;
typedef unsigned short ushort;

// ---------------- scratch (device globals) ----------------
__device__ float g_kp  [(size_t)BB * DD * KK];
__device__ float g_srcp[(size_t)BB * DD * KK];
__device__ float g_scol[KK];
__device__ float g_b1f [2 * DD];
__device__ float g_bqp [DD];

// single-plane fp16 weights
__device__ ushort g_wqp_h [(size_t)DD * DD];
__device__ ushort g_wk_h  [(size_t)DD * DD];
__device__ ushort g_ws1f_h[(size_t)(2 * DD) * (2 * DD)];
__device__ ushort g_ws2_h [(size_t)DD * (2 * DD)];
__device__ ushort g_w1b_h [(size_t)(2 * DD) * DD];
__device__ ushort g_wmTp  [(size_t)DD * DD];
// fp16 activations / operands
__device__ ushort g_xs   [(size_t)BB * NN * DD];
__device__ ushort g_qs   [(size_t)BB * NN * DD];
__device__ ushort g_msgs [(size_t)BB * NN * DD];
__device__ ushort g_hs   [(size_t)BB * NN * 2 * DD];
__device__ ushort g_srcpT[(size_t)BB * KK * DD];
__device__ ushort g_projT[(size_t)KK * NN];

// ---------------- helpers ----------------
__device__ __forceinline__ uint32_t smem_to_u32(const void* p) {
    uint32_t a;
    asm("{ .reg .u64 t; cvta.to.shared.u64 t, %1; cvt.u32.u64 %0, t; }"
        : "=r"(a) : "l"(p));
    return a;
}
__device__ __forceinline__ void sts_v4(uint32_t addr, uint4 v) {
    asm volatile("st.shared.v4.b32 [%0], {%1, %2, %3, %4};"
                 :: "r"(addr), "r"(v.x), "r"(v.y), "r"(v.z), "r"(v.w));
}
__device__ __forceinline__ void ldsm4(uint* r, uint32_t addr) {
    asm volatile("ldmatrix.sync.aligned.m8n8.x4.shared.b16 {%0,%1,%2,%3}, [%4];"
        : "=r"(r[0]), "=r"(r[1]), "=r"(r[2]), "=r"(r[3]) : "r"(addr));
}

// HMMA m16n8k16 fp16 -> fp32
__device__ __forceinline__ void mma16816(float* c, const uint* a, uint b0, uint b1) {
    asm volatile(
        "mma.sync.aligned.m16n8k16.row.col.f32.f16.f16.f32 "
        "{%0,%1,%2,%3}, {%4,%5,%6,%7}, {%8,%9}, {%0,%1,%2,%3};"
        : "+f"(c[0]), "+f"(c[1]), "+f"(c[2]), "+f"(c[3])
        : "r"(a[0]), "r"(a[1]), "r"(a[2]), "r"(a[3]), "r"(b0), "r"(b1));
}
__device__ __forceinline__ uint ex2_f16x2(uint t) {
    uint r;
    asm("ex2.approx.f16x2 %0, %1;" : "=r"(r) : "r"(t));
    return r;
}

// pack 8 consecutive fp32 -> 8 fp16 (one uint4 store)
__device__ __forceinline__ void cvt8(const float* __restrict__ in, ushort* __restrict__ out) {
    float4 f0 = *(const float4*)in;
    float4 f1 = *(const float4*)(in + 4);
    __half2 h0 = __floats2half2_rn(f0.x, f0.y);
    __half2 h1 = __floats2half2_rn(f0.z, f0.w);
    __half2 h2 = __floats2half2_rn(f1.x, f1.y);
    __half2 h3 = __floats2half2_rn(f1.z, f1.w);
    *(uint4*)out = make_uint4(*(uint*)&h0, *(uint*)&h1, *(uint*)&h2, *(uint*)&h3);
}

// ---------------------------------------------------------------------------
// Mega weight prep: 8 elems/thread, fully vectorized.
// regions: [0,512) wq(perm) | [512,1024) wk | [1024,2048) w2 | [2048,4096) w1
// ---------------------------------------------------------------------------
__global__ void prep_all(const float* __restrict__ wq, const float* __restrict__ wk,
                         const float* __restrict__ w2, const float* __restrict__ w1,
                         ushort* __restrict__ wqp, ushort* __restrict__ wkh,
                         ushort* __restrict__ ws2h,
                         ushort* __restrict__ w1a, ushort* __restrict__ w1b)
{
    const int cta = blockIdx.x;
    const int tid = threadIdx.x;
    if (cta < 512) {
        const int i = cta * 2048 + tid * 8;
        const int m = i >> 10, k = i & 1023;
        const int p = (m & 15) * 64 + (m >> 4);
        cvt8(wq + i, wqp + (size_t)p * DD + k);
    } else if (cta < 1024) {
        const int i = (cta - 512) * 2048 + tid * 8;
        cvt8(wk + i, wkh + i);
    } else if (cta < 2048) {
        const int i = (cta - 1024) * 2048 + tid * 8;
        cvt8(w2 + i, ws2h + i);
    } else {
        const int i = (cta - 2048) * 2048 + tid * 8;
        const int m = i >> 11, k = i & 2047;
        if (k < DD) cvt8(w1 + i, w1a + (size_t)m * (2 * DD) + k);
        else        cvt8(w1 + i, w1b + (size_t)m * DD + (k - DD));
    }
}

// ---------------------------------------------------------------------------
// Fused small prep:
// ctas [0,256): bias_fold | [256,288): colsum | [288,292): bias_perm
// ctas [292,804): zero srcp (float4)
// ---------------------------------------------------------------------------
__global__ void small_prep(const float* __restrict__ w1, const float* __restrict__ bm,
                           const float* __restrict__ b1, float* __restrict__ b1f,
                           const float* __restrict__ proj, float* __restrict__ scol,
                           const float* __restrict__ bq, float* __restrict__ bqp,
                           float* __restrict__ srcp)
{
    const int cta = blockIdx.x;
    const int tid = threadIdx.x;
    if (cta < 256) {
        const int m = cta * 8 + (tid >> 5);
        const int lane = tid & 31;
        float s = 0.f;
#pragma unroll 4
        for (int c = lane; c < DD; c += 32)
            s += w1[(size_t)m * (2 * DD) + DD + c] * bm[c];
#pragma unroll
        for (int o = 16; o; o >>= 1) s += __shfl_xor_sync(0xFFFFFFFFu, s, o);
        if (lane == 0) b1f[m] = b1[m] + s;
    } else if (cta < 288) {
        if (tid < KK) {
            const float* p = proj + (size_t)(cta - 256) * 128 * KK + tid;
            float s = 0.f;
#pragma unroll 8
            for (int m = 0; m < 128; m++) s += p[(size_t)m * KK];
            atomicAdd(&scol[tid], s);
        }
    } else if (cta < 292) {
        const int p = (cta - 288) * 256 + tid;
        const int d = (p & 63) * 16 + (p >> 6);
        bqp[p] = bq[d];
    } else {
        // zero srcp: 512 CTAs x 256 thr x 1 float4 = 2M floats
        const int idx = (cta - 292) * 256 + tid;
        *(float4*)(srcp + (size_t)idx * 4) = make_float4(0.f, 0.f, 0.f, 0.f);
    }
}

// fp32 [B, C, N] -> fp16 [B, N, C]
__global__ void transpose_half(const float* __restrict__ in, ushort* __restrict__ out,
                               int C, int Nw) {
    __shared__ float tile[32][33];
    const int b = blockIdx.z;
    const int n0 = blockIdx.x * 32, c0 = blockIdx.y * 32;
    const int tx = threadIdx.x, ty = threadIdx.y;
    const float* inb = in + ((size_t)b * C + c0) * Nw + n0;
#pragma unroll
    for (int i = 0; i < 32; i += 8)
        tile[ty + i][tx] = inb[(size_t)(ty + i) * Nw + tx];
    __syncthreads();
    ushort* ob = out + ((size_t)b * Nw + n0) * C + c0;
#pragma unroll
    for (int i = 0; i < 32; i += 8)
        ob[(size_t)(ty + i) * C + tx] = __half_as_ushort(__float2half_rn(tile[tx][ty + i]));
}

// Permuted merge transpose: out[p][j] = fp16(merge_w[j][c]), p=(c%16)*64+c/16
__global__ void transpose_perm(const float* __restrict__ in, ushort* __restrict__ out) {
    __shared__ float tile[32][33];
    const int n0 = blockIdx.x * 32, c0 = blockIdx.y * 32;
    const int tx = threadIdx.x, ty = threadIdx.y;
    const float* inb = in + (size_t)(c0) * DD + n0;
#pragma unroll
    for (int i = 0; i < 32; i += 8)
        tile[ty + i][tx] = inb[(size_t)(ty + i) * DD + tx];
    __syncthreads();
#pragma unroll
    for (int i = 0; i < 32; i += 8) {
        const int r = n0 + ty + i;
        const int p = (r & 15) * 64 + (r >> 4);
        out[(size_t)p * DD + c0 + tx] =
            __half_as_ushort(__float2half_rn(tile[tx][ty + i]));
    }
}

// ---------------------------------------------------------------------------
// Warp-level HMMA GEMM (single-plane fp16 A).
// MODE 0: fp32 out (+bias); MODE 1: +bias fp16-transpose out [B,Nw,M];
// MODE 2: +bias/BN/ReLU fp16-transpose out; MODE 3: plain-fp16 out [M,ostr];
// MODE 4: fp32 out + bias[m]*colS[n]  (colS passed via gamma).
// ---------------------------------------------------------------------------
#define STG_S 136

template <int MODE>
__global__ void __launch_bounds__(256, 2) hmma_gemm(
    const ushort* __restrict__ Aptr,
    const ushort* __restrict__ B1,
    const ushort* __restrict__ B2,
    const float* __restrict__ bias,
    const float* __restrict__ gamma,
    const float* __restrict__ beta,
    const float* __restrict__ mean,
    const float* __restrict__ var,
    float* __restrict__ outF,
    ushort* __restrict__ outT,
    int M, int Kd, int Nw, int K1, int ostr)
{
    constexpr uint32_t PLB   = 18432u;
    constexpr uint32_t SMBUF = 36864u;

    extern __shared__ char smem[];
    const uint32_t sb = smem_to_u32(smem);

    const int tid  = threadIdx.x;
    const int wid  = tid >> 5;
    const int lane = tid & 31;
    const int m0 = blockIdx.y * 128;
    const int n0 = blockIdx.x * 128;
    const int bb = blockIdx.z;

    const int wm = wid & 3;
    const int wn = wid >> 2;
    const int K2 = Kd - K1;
    const int fr = lane >> 2;
    const int fc = (lane & 3) * 2;

    float c[2][8][4];
#pragma unroll
    for (int mt = 0; mt < 2; mt++)
#pragma unroll
        for (int nt = 0; nt < 8; nt++)
#pragma unroll
            for (int j = 0; j < 4; j++) c[mt][nt][j] = 0.f;

    const int nc = Kd >> 6;
    uint4 pa[4], pb[4];

    auto ldg_tile = [&](int ch) {
        const int k0 = ch * 64;
        const ushort* Ab = Aptr + (size_t)m0 * Kd;
#pragma unroll
        for (int it = 0; it < 4; it++) {
            const int idx = it * 256 + tid;
            const int row = idx >> 3, q4 = idx & 7;
            pa[it] = *(const uint4*)(Ab + (size_t)row * Kd + k0 + q4 * 8);
        }
        const ushort* Bsrc; int kloc, kstride;
        if (k0 < K1) { Bsrc = B1; kloc = k0;      kstride = K1; }
        else         { Bsrc = B2; kloc = k0 - K1; kstride = K2; }
        const ushort* Bb = Bsrc + ((size_t)bb * Nw + n0) * kstride + kloc;
#pragma unroll
        for (int it = 0; it < 4; it++) {
            const int idx = it * 256 + tid;
            const int row = idx >> 3, q4 = idx & 7;
            pb[it] = *(const uint4*)(Bb + (size_t)row * kstride + q4 * 8);
        }
    };
    auto sts_tile = [&](int buf) {
        const uint32_t base = sb + buf * SMBUF;
#pragma unroll
        for (int it = 0; it < 4; it++) {
            const int idx = it * 256 + tid;
            const int row = idx >> 3, q4 = idx & 7;
            sts_v4(base + (uint32_t)row * 144 + q4 * 16, pa[it]);
            sts_v4(base + PLB + (uint32_t)row * 144 + q4 * 16, pb[it]);
        }
    };

    ldg_tile(0);
    sts_tile(0);
    __syncthreads();

    const uint32_t aOff = (uint32_t)(wm * 32 + (lane & 15)) * 144 + ((lane >> 4) & 1) * 16;
    const uint32_t bOff = (uint32_t)(wn * 64 + (lane & 7) + ((lane & 16) ? 8 : 0)) * 144
                        + ((lane & 8) ? 16 : 0);

    for (int ch = 0; ch < nc; ch++) {
        const uint32_t base = sb + (ch & 1) * SMBUF;
        if (ch + 1 < nc) ldg_tile(ch + 1);
#pragma unroll
        for (int ksb = 0; ksb < 128; ksb += 32) {
            uint ah[2][4];
            ldsm4(ah[0], base + aOff + ksb);
            ldsm4(ah[1], base + aOff + 2304 + ksb);
            uint bh[4][4];
#pragma unroll
            for (int np = 0; np < 4; np++)
                ldsm4(bh[np], base + PLB + bOff + np * 2304 + ksb);
#pragma unroll
            for (int np = 0; np < 4; np++)
#pragma unroll
                for (int sub = 0; sub < 2; sub++) {
                    const int nt = np * 2 + sub;
                    const uint b0 = bh[np][sub * 2], b1 = bh[np][sub * 2 + 1];
#pragma unroll
                    for (int mt = 0; mt < 2; mt++)
                        mma16816(c[mt][nt], ah[mt], b0, b1);
                }
        }
        if (ch + 1 < nc) {
            sts_tile((ch + 1) & 1);
            __syncthreads();
        }
    }

    // ---- epilogue ----
    if (MODE == 0 || MODE == 4) {
        const int cm = m0 + wm * 32 + fr;
        const int cn = n0 + wn * 64 + fc;
#pragma unroll
        for (int mt = 0; mt < 2; mt++) {
            const int mlo = cm + mt * 16;
            const int mhi = mlo + 8;
            const float bi0 = bias[mlo], bi1 = bias[mhi];
#pragma unroll
            for (int nt = 0; nt < 8; nt++) {
                const int n = cn + nt * 8;
                float s0 = 1.f, s1 = 1.f;
                if (MODE == 4) { s0 = gamma[n]; s1 = gamma[n + 1]; }
                *(float2*)(outF + ((size_t)bb * M + mlo) * ostr + n) =
                    make_float2(c[mt][nt][0] + bi0 * s0, c[mt][nt][1] + bi0 * s1);
                *(float2*)(outF + ((size_t)bb * M + mhi) * ostr + n) =
                    make_float2(c[mt][nt][2] + bi1 * s0, c[mt][nt][3] + bi1 * s1);
            }
        }
    } else if (MODE == 3) {
        ushort* ob = outT;
        const int cm = m0 + wm * 32 + fr;
        const int cn = n0 + wn * 64 + fc;
#pragma unroll
        for (int mt = 0; mt < 2; mt++) {
            const int mlo = cm + mt * 16;
            const int mhi = mlo + 8;
#pragma unroll
            for (int nt = 0; nt < 8; nt++) {
                const int n = cn + nt * 8;
                ob[(size_t)mlo * ostr + n]     = __half_as_ushort(__float2half_rn(c[mt][nt][0]));
                ob[(size_t)mlo * ostr + n + 1] = __half_as_ushort(__float2half_rn(c[mt][nt][1]));
                ob[(size_t)mhi * ostr + n]     = __half_as_ushort(__float2half_rn(c[mt][nt][2]));
                ob[(size_t)mhi * ostr + n + 1] = __half_as_ushort(__float2half_rn(c[mt][nt][3]));
            }
        }
    } else {
        float* stg = (float*)smem;
        uint* ob = (uint*)(outT + (size_t)bb * Nw * M);
#pragma unroll
        for (int p = 0; p < 2; p++) {
            __syncthreads();
            if (wn == p) {
#pragma unroll
                for (int mt = 0; mt < 2; mt++) {
                    const int mloL = wm * 32 + mt * 16 + fr;
                    const int mhiL = mloL + 8;
                    const int mlo = m0 + mloL, mhi = m0 + mhiL;
                    float sc0 = 1.f, sh0 = bias[mlo];
                    float sc1 = 1.f, sh1 = bias[mhi];
                    if (MODE == 2) {
                        sc0 = gamma[mlo] * rsqrtf(var[mlo] + 1e-3f);
                        sh0 = beta[mlo] + (sh0 - mean[mlo]) * sc0;
                        sc1 = gamma[mhi] * rsqrtf(var[mhi] + 1e-3f);
                        sh1 = beta[mhi] + (sh1 - mean[mhi]) * sc1;
                    }
#pragma unroll
                    for (int nt = 0; nt < 8; nt++) {
                        const int nl = fc + nt * 8;
                        float v0 = fmaf(c[mt][nt][0], sc0, sh0);
                        float v1 = fmaf(c[mt][nt][1], sc0, sh0);
                        float v2 = fmaf(c[mt][nt][2], sc1, sh1);
                        float v3 = fmaf(c[mt][nt][3], sc1, sh1);
                        if (MODE == 2) {
                            v0 = fmaxf(v0, 0.f); v1 = fmaxf(v1, 0.f);
                            v2 = fmaxf(v2, 0.f); v3 = fmaxf(v3, 0.f);
                        }
                        stg[(nl)     * STG_S + mloL] = v0;
                        stg[(nl + 1) * STG_S + mloL] = v1;
                        stg[(nl)     * STG_S + mhiL] = v2;
                        stg[(nl + 1) * STG_S + mhiL] = v3;
                    }
                }
            }
            __syncthreads();
            const int nb = n0 + p * 64;
#pragma unroll 4
            for (int i = 0; i < 16; i++) {
                const int idx = i * 256 + tid;
                const int nn = idx >> 6;
                const int mp = idx & 63;
                const float* s = stg + nn * STG_S + mp * 2;
                const uint u = (uint)__half_as_ushort(__float2half_rn(s[0]))
                             | ((uint)__half_as_ushort(__float2half_rn(s[1])) << 16);
                ob[(size_t)(nb + nn) * (M >> 1) + (m0 >> 1) + mp] = u;
            }
        }
    }
}

// ---------------------------------------------------------------------------
// Split-K fp16 HMMA: srcp[r,c] += fp16(source[r,:]) . projT[c,:]
// ---------------------------------------------------------------------------
__global__ void __launch_bounds__(256, 2) hmma_splitk(
    const float* __restrict__ A,
    const ushort* __restrict__ Bp,
    float* __restrict__ C)
{
    constexpr uint32_t PLB = 18432;
    constexpr uint32_t SMBUF = 36864;
    extern __shared__ char smem[];
    const uint32_t sb = smem_to_u32(smem);

    const int tid  = threadIdx.x;
    const int wid  = tid >> 5;
    const int lane = tid & 31;
    const int m0 = blockIdx.y * 128;
    const int kbase = blockIdx.x * 512;
    const int Kd = NN;

    const int wm = wid & 3;
    const int wn = wid >> 2;
    const int fr = lane >> 2;
    const int fc = (lane & 3) * 2;

    float c[2][8][4];
#pragma unroll
    for (int mt = 0; mt < 2; mt++)
#pragma unroll
        for (int nt = 0; nt < 8; nt++)
#pragma unroll
            for (int j = 0; j < 4; j++) c[mt][nt][j] = 0.f;

    uint4 pa[4], pb[4];
    auto ldg_tile = [&](int ch) {
        const int k0 = kbase + ch * 64;
        const float* Ab = A + (size_t)m0 * Kd;
#pragma unroll
        for (int it = 0; it < 4; it++) {
            const int idx = it * 256 + tid;
            const int row = idx >> 3, q4 = idx & 7;
            const float* ap = Ab + (size_t)row * Kd + k0 + q4 * 8;
            float4 f0 = *(const float4*)ap;
            float4 f1 = *(const float4*)(ap + 4);
            __half2 h0 = __floats2half2_rn(f0.x, f0.y);
            __half2 h1 = __floats2half2_rn(f0.z, f0.w);
            __half2 h2 = __floats2half2_rn(f1.x, f1.y);
            __half2 h3 = __floats2half2_rn(f1.z, f1.w);
            pa[it] = make_uint4(*(uint*)&h0, *(uint*)&h1, *(uint*)&h2, *(uint*)&h3);
        }
#pragma unroll
        for (int it = 0; it < 4; it++) {
            const int idx = it * 256 + tid;
            const int row = idx >> 3, q4 = idx & 7;
            pb[it] = *(const uint4*)(Bp + (size_t)row * Kd + k0 + q4 * 8);
        }
    };
    auto sts_tile = [&](int buf) {
        const uint32_t base = sb + buf * SMBUF;
#pragma unroll
        for (int it = 0; it < 4; it++) {
            const int idx = it * 256 + tid;
            const int row = idx >> 3, q4 = idx & 7;
            sts_v4(base + (uint32_t)row * 144 + q4 * 16, pa[it]);
            sts_v4(base + PLB + (uint32_t)row * 144 + q4 * 16, pb[it]);
        }
    };

    ldg_tile(0);
    sts_tile(0);
    __syncthreads();

    const uint32_t aOff = (uint32_t)(wm * 32 + (lane & 15)) * 144 + ((lane >> 4) & 1) * 16;
    const uint32_t bOff = (uint32_t)(wn * 64 + (lane & 7) + ((lane & 16) ? 8 : 0)) * 144
                        + ((lane & 8) ? 16 : 0);

    for (int ch = 0; ch < 8; ch++) {
        const uint32_t base = sb + (ch & 1) * SMBUF;
        if (ch + 1 < 8) ldg_tile(ch + 1);
#pragma unroll
        for (int ksb = 0; ksb < 128; ksb += 32) {
            uint ah[2][4];
            ldsm4(ah[0], base + aOff + ksb);
            ldsm4(ah[1], base + aOff + 2304 + ksb);
            uint bh[4][4];
#pragma unroll
            for (int np = 0; np < 4; np++)
                ldsm4(bh[np], base + PLB + bOff + np * 2304 + ksb);
#pragma unroll
            for (int np = 0; np < 4; np++)
#pragma unroll
                for (int sub = 0; sub < 2; sub++) {
                    const int nt = np * 2 + sub;
#pragma unroll
                    for (int mt = 0; mt < 2; mt++)
                        mma16816(c[mt][nt], ah[mt], bh[np][sub * 2], bh[np][sub * 2 + 1]);
                }
        }
        if (ch + 1 < 8) {
            sts_tile((ch + 1) & 1);
            __syncthreads();
        }
    }

    const int cm = m0 + wm * 32 + fr;
    const int cn = wn * 64 + fc;
#pragma unroll
    for (int mt = 0; mt < 2; mt++) {
        const int mlo = cm + mt * 16;
        const int mhi = mlo + 8;
#pragma unroll
        for (int nt = 0; nt < 8; nt++) {
            const int n = cn + nt * 8;
            atomicAdd(&C[(size_t)mlo * KK + n],     c[mt][nt][0]);
            atomicAdd(&C[(size_t)mlo * KK + n + 1], c[mt][nt][1]);
            atomicAdd(&C[(size_t)mhi * KK + n],     c[mt][nt][2]);
            atomicAdd(&C[(size_t)mhi * KK + n + 1], c[mt][nt][3]);
        }
    }
}

// ---------------------------------------------------------------------------
// Tensor-core attention (fp16x2 MUFU exp, 2 CTAs/SM, reg-reuse).
// Exact copy of the 900.9us winner's attn (scalar K loads).
// ---------------------------------------------------------------------------
#define AT_Q   0
#define AT_K1  18432
#define AT_K2  36864
#define AT_RS  54272
#define AT_SMEM 54784

__global__ void __launch_bounds__(256, 2) attn_mma(
    const ushort* __restrict__ qs,
    const float* __restrict__ kp,
    ushort* __restrict__ msgs)
{
    extern __shared__ char smem[];
    const uint32_t sb = smem_to_u32(smem);
    float* rowsum = (float*)(smem + AT_RS);

    const int tid = threadIdx.x;
    const int wid = tid >> 5, lane = tid & 31;
    const int wm = wid & 3, wn = wid >> 2;
    const int fr = lane >> 2, fc = (lane & 3) * 2;
    const int n0 = blockIdx.x * 128;
    const int h = blockIdx.y;
    const int b = blockIdx.z;

    // Q tile [128][64] fp16 -> smem stride 144B
    {
        const ushort* qb = qs + ((size_t)b * NN + n0) * DD + (size_t)h * DHH;
#pragma unroll
        for (int it = 0; it < 4; it++) {
            const int idx = it * 256 + tid;
            const int row = idx >> 3, q4 = idx & 7;
            uint4 v = *(const uint4*)(qb + (size_t)row * DD + q4 * 8);
            sts_v4(sb + AT_Q + (uint32_t)row * 144 + q4 * 16, v);
        }
    }
    // K fp32 [64 dh][128 kk] -> K1 [kk][dh] (144B stride) + K2 [dh][kk] (272B)
    {
        const float* kb = kp + ((size_t)b * DD + h) * KK;
        ushort* K1 = (ushort*)(smem + AT_K1);
        ushort* K2 = (ushort*)(smem + AT_K2);
#pragma unroll 8
        for (int i = 0; i < 32; i++) {
            const int e = i * 256 + tid;
            const int dh = e >> 7, kk = e & 127;
            const ushort v = __half_as_ushort(
                __float2half_rn(kb[(size_t)dh * HH * KK + kk]));
            K2[dh * 136 + kk] = v;
            K1[kk * 72 + dh] = v;
        }
    }
    if (tid < 128) rowsum[tid] = 0.f;
    __syncthreads();

    // MMA1: S[n][kk]
    float c[2][8][4];
#pragma unroll
    for (int mt = 0; mt < 2; mt++)
#pragma unroll
        for (int nt = 0; nt < 8; nt++)
#pragma unroll
            for (int j = 0; j < 4; j++) c[mt][nt][j] = 0.f;

    const uint32_t aOff = (uint32_t)(wm * 32 + (lane & 15)) * 144 + ((lane >> 4) & 1) * 16;
    const uint32_t bOff = (uint32_t)(wn * 64 + (lane & 7) + ((lane & 16) ? 8 : 0)) * 144
                        + ((lane & 8) ? 16 : 0);
#pragma unroll
    for (int ksb = 0; ksb < 128; ksb += 32) {
        uint ah[2][4];
        ldsm4(ah[0], sb + AT_Q + aOff + ksb);
        ldsm4(ah[1], sb + AT_Q + aOff + 2304 + ksb);
#pragma unroll
        for (int np = 0; np < 4; np++) {
            uint bh[4];
            ldsm4(bh, sb + AT_K1 + bOff + np * 2304 + ksb);
#pragma unroll
            for (int sub = 0; sub < 2; sub++)
#pragma unroll
                for (int mt = 0; mt < 2; mt++)
                    mma16816(c[mt][np * 2 + sub], ah[mt], bh[sub * 2], bh[sub * 2 + 1]);
        }
    }

    // P = 2^(s*C1 + C2) via ex2.approx.f16x2 ; rowsum fp32
    const float C1 = 0.18033688f;    // log2(e)/8
    const float C2 = -5.7707801f;    // -4*log2(e)
    uint ph[2][8][2];
#pragma unroll
    for (int mt = 0; mt < 2; mt++) {
        float r0 = 0.f, r1 = 0.f;
#pragma unroll
        for (int nt = 0; nt < 8; nt++) {
            const float t0 = fmaf(c[mt][nt][0], C1, C2);
            const float t1 = fmaf(c[mt][nt][1], C1, C2);
            const float t2 = fmaf(c[mt][nt][2], C1, C2);
            const float t3 = fmaf(c[mt][nt][3], C1, C2);
            const __half2 ta = __floats2half2_rn(t0, t1);
            const __half2 tb = __floats2half2_rn(t2, t3);
            const uint ea = ex2_f16x2(*(const uint*)&ta);
            const uint eb = ex2_f16x2(*(const uint*)&tb);
            ph[mt][nt][0] = ea;
            ph[mt][nt][1] = eb;
            const float2 fa = __half22float2(*(const __half2*)&ea);
            const float2 fb = __half22float2(*(const __half2*)&eb);
            r0 += fa.x + fa.y;
            r1 += fb.x + fb.y;
        }
        r0 += __shfl_xor_sync(0xFFFFFFFFu, r0, 1);
        r0 += __shfl_xor_sync(0xFFFFFFFFu, r0, 2);
        r1 += __shfl_xor_sync(0xFFFFFFFFu, r1, 1);
        r1 += __shfl_xor_sync(0xFFFFFFFFu, r1, 2);
        if ((lane & 3) == 0) {
            atomicAdd(&rowsum[wm * 32 + mt * 16 + fr], r0);
            atomicAdd(&rowsum[wm * 32 + mt * 16 + fr + 8], r1);
        }
    }

    // MMA2: reuse c as O accumulators
#pragma unroll
    for (int mt = 0; mt < 2; mt++)
#pragma unroll
        for (int nt = 0; nt < 8; nt++)
#pragma unroll
            for (int j = 0; j < 4; j++) c[mt][nt][j] = 0.f;

    const uint32_t b2Off = (uint32_t)((lane & 7) + ((lane & 16) ? 8 : 0)) * 272
                         + ((lane & 8) ? 16 : 0) + (uint32_t)wn * 128;
#pragma unroll
    for (int s = 0; s < 4; s++) {
        uint a2[2][4];
#pragma unroll
        for (int mt = 0; mt < 2; mt++) {
            a2[mt][0] = ph[mt][2 * s][0];
            a2[mt][1] = ph[mt][2 * s][1];
            a2[mt][2] = ph[mt][2 * s + 1][0];
            a2[mt][3] = ph[mt][2 * s + 1][1];
        }
#pragma unroll
        for (int np = 0; np < 4; np++) {
            uint bh[4];
            ldsm4(bh, sb + AT_K2 + b2Off + (uint32_t)np * 16 * 272 + s * 32);
#pragma unroll
            for (int sub = 0; sub < 2; sub++)
#pragma unroll
                for (int mt = 0; mt < 2; mt++)
                    mma16816(c[mt][np * 2 + sub], a2[mt], bh[sub * 2], bh[sub * 2 + 1]);
        }
    }

    // merge partials, normalize, write fp16 head-major
    __syncthreads();
    float* stg = (float*)smem;
    if (tid < 128) rowsum[tid] = 1.f / rowsum[tid];
    const int mb = wm * 32 + fr;
    if (wn == 0) {
#pragma unroll
        for (int mt = 0; mt < 2; mt++)
#pragma unroll
            for (int nt = 0; nt < 8; nt++) {
                const int col = nt * 8 + fc;
                stg[(mb + mt * 16)     * 68 + col]     = c[mt][nt][0];
                stg[(mb + mt * 16)     * 68 + col + 1] = c[mt][nt][1];
                stg[(mb + mt * 16 + 8) * 68 + col]     = c[mt][nt][2];
                stg[(mb + mt * 16 + 8) * 68 + col + 1] = c[mt][nt][3];
            }
    }
    __syncthreads();
    if (wn == 1) {
#pragma unroll
        for (int mt = 0; mt < 2; mt++)
#pragma unroll
            for (int nt = 0; nt < 8; nt++) {
                const int col = nt * 8 + fc;
                stg[(mb + mt * 16)     * 68 + col]     += c[mt][nt][0];
                stg[(mb + mt * 16)     * 68 + col + 1] += c[mt][nt][1];
                stg[(mb + mt * 16 + 8) * 68 + col]     += c[mt][nt][2];
                stg[(mb + mt * 16 + 8) * 68 + col + 1] += c[mt][nt][3];
            }
    }
    __syncthreads();

    uint* ob = (uint*)(msgs + ((size_t)b * NN + n0) * DD + (size_t)h * DHH);
#pragma unroll 4
    for (int i = 0; i < 16; i++) {
        const int idx = i * 256 + tid;
        const int nn = idx >> 5;
        const int dq = idx & 31;
        const float inv = rowsum[nn];
        const float v0 = stg[nn * 68 + dq * 2]     * inv;
        const float v1 = stg[nn * 68 + dq * 2 + 1] * inv;
        const uint u = (uint)__half_as_ushort(__float2half_rn(v0))
                     | ((uint)__half_as_ushort(__float2half_rn(v1)) << 16);
        ob[(size_t)nn * (DD / 2) + dq] = u;
    }
}

// ---------------------------------------------------------------------------
extern "C" void kernel_launch(void* const* d_in, const int* in_sizes, int n_in,
                              void* d_out, int out_size)
{
    const float* x       = (const float*)d_in[0];
    const float* source  = (const float*)d_in[1];
    const float* to_q_w  = (const float*)d_in[2];
    const float* to_q_b  = (const float*)d_in[3];
    const float* to_k_w  = (const float*)d_in[4];
    const float* to_k_b  = (const float*)d_in[5];
    const float* proj_k  = (const float*)d_in[6];
    const float* merge_w = (const float*)d_in[7];
    const float* merge_b = (const float*)d_in[8];
    const float* mlp_w1  = (const float*)d_in[9];
    const float* mlp_b1  = (const float*)d_in[10];
    const float* bn_g    = (const float*)d_in[11];
    const float* bn_b    = (const float*)d_in[12];
    const float* bn_m    = (const float*)d_in[13];
    const float* bn_v    = (const float*)d_in[14];
    const float* mlp_w2  = (const float*)d_in[15];
    const float* mlp_b2  = (const float*)d_in[16];
    float* out = (float*)d_out;

    float *kp, *srcp, *scol, *b1f, *bqp;
    ushort *wqp, *wkh, *ws1fh, *ws2h, *w1bh, *wmTp, *xs, *qs, *msgs, *hs, *srcpT, *projT;
    cudaGetSymbolAddress((void**)&kp,   g_kp);
    cudaGetSymbolAddress((void**)&srcp, g_srcp);
    cudaGetSymbolAddress((void**)&scol, g_scol);
    cudaGetSymbolAddress((void**)&b1f,  g_b1f);
    cudaGetSymbolAddress((void**)&bqp,  g_bqp);
    cudaGetSymbolAddress((void**)&wqp,  g_wqp_h);
    cudaGetSymbolAddress((void**)&wkh,  g_wk_h);
    cudaGetSymbolAddress((void**)&ws1fh,g_ws1f_h);
    cudaGetSymbolAddress((void**)&ws2h, g_ws2_h);
    cudaGetSymbolAddress((void**)&w1bh, g_w1b_h);
    cudaGetSymbolAddress((void**)&wmTp, g_wmTp);
    cudaGetSymbolAddress((void**)&xs,   g_xs);
    cudaGetSymbolAddress((void**)&qs,   g_qs);
    cudaGetSymbolAddress((void**)&msgs, g_msgs);
    cudaGetSymbolAddress((void**)&hs,   g_hs);
    cudaGetSymbolAddress((void**)&srcpT,g_srcpT);
    cudaGetSymbolAddress((void**)&projT,g_projT);

    const int SM1 = 2 * 36864;
    cudaFuncSetAttribute(hmma_gemm<0>, cudaFuncAttributeMaxDynamicSharedMemorySize, SM1);
    cudaFuncSetAttribute(hmma_gemm<1>, cudaFuncAttributeMaxDynamicSharedMemorySize, SM1);
    cudaFuncSetAttribute(hmma_gemm<2>, cudaFuncAttributeMaxDynamicSharedMemorySize, SM1);
    cudaFuncSetAttribute(hmma_gemm<3>, cudaFuncAttributeMaxDynamicSharedMemorySize, SM1);
    cudaFuncSetAttribute(hmma_gemm<4>, cudaFuncAttributeMaxDynamicSharedMemorySize, SM1);
    cudaFuncSetAttribute(hmma_splitk, cudaFuncAttributeMaxDynamicSharedMemorySize, SM1);
    cudaFuncSetAttribute(attn_mma, cudaFuncAttributeMaxDynamicSharedMemorySize, AT_SMEM);

    // 0) fused weight prep + fused small prep (bias_fold/colsum/bias_perm/srcp-zero)
    prep_all<<<4096, 256>>>(to_q_w, to_k_w, mlp_w2, mlp_w1,
                            wqp, wkh, ws2h, ws1fh, w1bh);
    cudaMemsetAsync(scol, 0, sizeof(float) * KK);
    small_prep<<<804, 256>>>(mlp_w1, merge_b, mlp_b1, b1f, proj_k, scol,
                             to_q_b, bqp, srcp);
    transpose_perm<<<dim3(DD / 32, DD / 32), dim3(32, 8)>>>(merge_w, wmTp);

    // W1c = W1b @ Wm (perm cols) -> ws1fh[m][1024:2048]  (known-good single kernel)
    hmma_gemm<3><<<dim3(DD / 128, (2 * DD) / 128, 1), 256, SM1>>>(
        w1bh, wmTp, wmTp, nullptr, nullptr, nullptr, nullptr, nullptr,
        nullptr, ws1fh + DD, 2 * DD, DD, DD, DD, 2 * DD);

    // x transpose, proj transpose
    transpose_half<<<dim3(NN / 32, DD / 32, BB), dim3(32, 8)>>>(x, xs, DD, NN);
    transpose_half<<<dim3(KK / 32, NN / 32, 1), dim3(32, 8)>>>(proj_k, projT, NN, KK);

    // 1) Linformer fold: kp = Wk @ (src @ proj) + bk * colsum(proj)
    hmma_splitk<<<dim3(8, (BB * DD) / 128), 256, SM1>>>(source, projT, srcp);
    transpose_half<<<dim3(KK / 32, DD / 32, BB), dim3(32, 8)>>>(srcp, srcpT, DD, KK);
    hmma_gemm<4><<<dim3(1, DD / 128, BB), 256, SM1>>>(
        wkh, srcpT, srcpT, to_k_b, scol, nullptr, nullptr, nullptr,
        kp, nullptr, DD, DD, KK, DD, KK);

    // 2) q = Wq @ x + bq  (fp16 head-major transposed out)
    hmma_gemm<1><<<dim3(NN / 128, DD / 128, BB), 256, SM1>>>(
        wqp, xs, xs, bqp, nullptr, nullptr, nullptr, nullptr,
        nullptr, qs, DD, DD, NN, DD, 0);

    // 3) tensor-core attention -> msgs fp16 head-major
    attn_mma<<<dim3(NN / 128, HH, BB), 256, AT_SMEM>>>(qs, kp, msgs);

    // 4) h = relu(BN([W1a | W1c'] @ concat(x, msg) + b1'))
    hmma_gemm<2><<<dim3(NN / 128, (2 * DD) / 128, BB), 256, SM1>>>(
        ws1fh, xs, msgs, b1f, bn_g, bn_b, bn_m, bn_v,
        nullptr, hs, 2 * DD, 2 * DD, NN, DD, 0);

    // 5) out = W2 @ h + b2  (fp32 out)
    hmma_gemm<0><<<dim3(NN / 128, DD / 128, BB), 256, SM1>>>(
        ws2h, hs, hs, mlp_b2, nullptr, nullptr, nullptr, nullptr,
        out, nullptr, DD, 2 * DD, NN, 2 * DD, NN);
}